// round 5
// baseline (speedup 1.0000x reference)
#include <cuda_runtime.h>
#include <math.h>

// Problem constants (fixed shapes from reference)
#define VSZ 50000
#define DIM 300
#define DP  304      // padded dim (zero-filled 300..303)
#define BB  256
#define QQ  16
#define TT_TOT 1024
#define KK  11
#define TTILE 256    // tokens per block
#define NSPLIT 4     // blocks per (b,side)
#define CH  8        // dims per smem chunk (double-buffered)
#define NCH (DP/CH)  // 38
#define DTSTRIDE 260 // words; bank = (4*gd + tb) mod 32 -> conflict-free gather STS

// Packed fp32x2 FMA (sm_103a FFMA2; component-wise, rounding identical to fmaf)
#define FMA2(acc, a, b) asm("fma.rn.f32x2 %0, %1, %2, %0;" : "+l"(acc) : "l"(a), "l"(b))
#define DUP2(dst, s)    asm("mov.b64 %0, {%1, %1};" : "=l"(dst) : "r"(s))
#define UNPK2(lo, hi, v) asm("mov.b64 {%0, %1}, %2;" : "=f"(lo), "=f"(hi) : "l"(v))

// Pre-normalized embedding table (~61.9 MB scratch; static __device__ allowed)
__device__ float g_embn[(size_t)VSZ * DP];
// Per-block partials: [2048][16][12]  (q-major; [q][0..10]=doc_k, [q][11]=sim-sum)
__device__ float g_part[(size_t)BB * 2 * NSPLIT * QQ * 12];

// ---------------------------------------------------------------------------
// Kernel 1: normalize emb rows into g_embn, padded to DP with zeros.
// ---------------------------------------------------------------------------
__global__ __launch_bounds__(256) void normalize_emb_kernel(const float* __restrict__ emb) {
    int row  = blockIdx.x * 8 + (threadIdx.x >> 5);
    int lane = threadIdx.x & 31;
    if (row >= VSZ) return;
    const float* src = emb + (size_t)row * DIM;
    float v[10];
    float ssq = 0.f;
#pragma unroll
    for (int j = 0; j < 10; j++) {
        int d = lane + 32 * j;
        v[j] = (d < DIM) ? src[d] : 0.f;
        ssq += v[j] * v[j];
    }
#pragma unroll
    for (int off = 16; off; off >>= 1) ssq += __shfl_xor_sync(0xffffffffu, ssq, off);
    float scale = 1.f / (sqrtf(ssq) + 1e-9f);
    float* dst = g_embn + (size_t)row * DP;
#pragma unroll
    for (int j = 0; j < 10; j++) {
        int d = lane + 32 * j;
        if (d < DP) dst[d] = (d < DIM) ? v[j] * scale : 0.f;
    }
}

// ---------------------------------------------------------------------------
// Kernel 2: one block per (b, side, tile). 256 threads.
// Thread tile: 4 q (as 2 packed q-pairs) x tokens {2u,2u+1,128+2u,128+2u+1}.
// Gather is software-pipelined through a double-buffered smem tile.
// ---------------------------------------------------------------------------
__global__ __launch_bounds__(256, 2) void knrm_main_kernel(
    const int* __restrict__ posdoc, const int* __restrict__ negdoc,
    const int* __restrict__ query,
    const float* __restrict__ mus, const float* __restrict__ sigmas)
{
    __shared__ __align__(16) float qt[DP][QQ];            // transposed queries, 19456 B
    __shared__ __align__(16) float dt[2][CH * DTSTRIDE];  // ping-pong doc tiles, 16640 B
    __shared__ __align__(16) float sdm[TTILE];            // doc pad mask
    __shared__ int   stok[TTILE];
    __shared__ float sqm[QQ];
    __shared__ float swarp[8][4][12];                     // per-warp partials (fixed-order reduce)
    __shared__ float smu[KK], sc2[KK];

    const int tid   = threadIdx.x;
    const int bx    = blockIdx.x;
    const int tile  = bx & (NSPLIT - 1);
    const int pairI = bx >> 2;              // b*2+side
    const int b     = pairI >> 1;
    const int side  = pairI & 1;
    const int* doc  = (side ? negdoc : posdoc) + b * TT_TOT + tile * TTILE;
    const int* qtok = query + b * QQ;

    if (tid < KK) {
        float s = sigmas[tid];
        smu[tid] = mus[tid];
        sc2[tid] = -0.5f / (s * s);
    }
    if (tid < QQ) sqm[tid] = (qtok[tid] != 0) ? 1.f : 0.f;

    // Doc tokens + pad mask for this block's 256 tokens
    {
        int tk = doc[tid];
        stok[tid] = tk;
        sdm[tid]  = (tk != 0) ? 1.f : 0.f;
    }

    // Transposed normalized query tile (coalesced gmem reads)
#pragma unroll 1
    for (int q = 0; q < QQ; q++) {
        const float* src = g_embn + (size_t)qtok[q] * DP;
        for (int d = tid; d < DP; d += 256) qt[d][q] = src[d];
    }
    __syncthreads();

    // Gather-role indices: lane gd in 0..7 loads dim ch*8+gd of 8 tokens
    const int gd = tid & 7;
    const int tb = tid >> 3;            // 0..31
    int toks[CH];
#pragma unroll
    for (int r = 0; r < CH; r++) toks[r] = stok[tb + 32 * r];

    // Compute-role indices
    const int qg = tid >> 6;            // q group (0..3), constant per warp
    const int u  = tid & 63;

    // Packed accumulators: acc2[p][i] = (sim[q=qg*4+2p][tok i], sim[q=qg*4+2p+1][tok i])
    unsigned long long acc2[2][4];
#pragma unroll
    for (int p = 0; p < 2; p++)
#pragma unroll
        for (int i = 0; i < 4; i++) acc2[p][i] = 0ull;

    // Pipeline prologue: fetch chunk 0 into registers
    float g[CH];
#pragma unroll
    for (int r = 0; r < CH; r++)
        g[r] = g_embn[(size_t)toks[r] * DP + gd];

#pragma unroll 1
    for (int ch = 0; ch < NCH; ch++) {
        float* db = dt[ch & 1];
        // Drain register stage into this chunk's buffer (conflict-free STS)
#pragma unroll
        for (int r = 0; r < CH; r++)
            db[gd * DTSTRIDE + tb + 32 * r] = g[r];
        __syncthreads();

        // Issue next chunk's gathers; they fly under the FFMA2 block below
        if (ch + 1 < NCH) {
            const size_t cb = (size_t)((ch + 1) * CH + gd);
#pragma unroll
            for (int r = 0; r < CH; r++)
                g[r] = g_embn[(size_t)toks[r] * DP + cb];
        }

        const int cbase = ch * CH;
#pragma unroll
        for (int d = 0; d < CH; d++) {
            // Two ready-packed q-pairs via one 128-bit broadcast load
            const ulonglong2 qp = *(const ulonglong2*)&qt[cbase + d][qg * 4];
            const uint2 dva = *(const uint2*)&db[d * DTSTRIDE + 2 * u];        // conflict-free
            const uint2 dvb = *(const uint2*)&db[d * DTSTRIDE + 128 + 2 * u];  // conflict-free
            unsigned long long t0, t1, t2, t3;
            DUP2(t0, dva.x); DUP2(t1, dva.y); DUP2(t2, dvb.x); DUP2(t3, dvb.y);
            FMA2(acc2[0][0], qp.x, t0); FMA2(acc2[0][1], qp.x, t1);
            FMA2(acc2[0][2], qp.x, t2); FMA2(acc2[0][3], qp.x, t3);
            FMA2(acc2[1][0], qp.y, t0); FMA2(acc2[1][1], qp.y, t1);
            FMA2(acc2[1][2], qp.y, t2); FMA2(acc2[1][3], qp.y, t3);
        }
        // no second barrier: next iteration stores into the other buffer
    }

    // Unpack packed accumulators: accf[j][i], j = 2p + (hi ? 1 : 0)
    float accf[4][4];
#pragma unroll
    for (int p = 0; p < 2; p++)
#pragma unroll
        for (int i = 0; i < 4; i++)
            UNPK2(accf[2 * p][i], accf[2 * p + 1][i], acc2[p][i]);

    // RBF kernel bank + accumulation (masked pairs contribute k(0), matching ref)
    float dock[4][KK];
    float ssm[4];
    {
        const float2 dma = *(const float2*)&sdm[2 * u];
        const float2 dmb = *(const float2*)&sdm[128 + 2 * u];
        const float dmv[4] = {dma.x, dma.y, dmb.x, dmb.y};
#pragma unroll
        for (int j = 0; j < 4; j++) {
            ssm[j] = 0.f;
#pragma unroll
            for (int k = 0; k < KK; k++) dock[j][k] = 0.f;
            const float qm = sqm[qg * 4 + j];
#pragma unroll
            for (int i = 0; i < 4; i++) {
                float s = accf[j][i] * qm * dmv[i];
                ssm[j] += s;
#pragma unroll
                for (int k = 0; k < KK; k++) {
                    float df = s - smu[k];
                    dock[j][k] += __expf(df * df * sc2[k]);
                }
            }
        }
    }

    // Warp butterfly reduce (all lanes of a warp share qg) -> per-warp slots
#pragma unroll
    for (int j = 0; j < 4; j++) {
#pragma unroll
        for (int off = 16; off; off >>= 1) ssm[j] += __shfl_xor_sync(0xffffffffu, ssm[j], off);
#pragma unroll
        for (int k = 0; k < KK; k++) {
#pragma unroll
            for (int off = 16; off; off >>= 1) dock[j][k] += __shfl_xor_sync(0xffffffffu, dock[j][k], off);
        }
    }
    const int wid = tid >> 5;
    if ((tid & 31) == 0) {
#pragma unroll
        for (int j = 0; j < 4; j++) {
            swarp[wid][j][11] = ssm[j];
#pragma unroll
            for (int k = 0; k < KK; k++) swarp[wid][j][k] = dock[j][k];
        }
    }
    __syncthreads();

    // Fixed-order combine of the two warps owning each q group -> global partials
    if (tid < QQ * 12) {
        const int q  = tid / 12;
        const int kk = tid - q * 12;
        const int w0 = (q >> 2) * 2;     // q group g is owned by warps 2g, 2g+1
        const int j  = q & 3;
        g_part[(size_t)bx * (QQ * 12) + tid] = swarp[w0][j][kk] + swarp[w0 + 1][j][kk];
    }
}

// ---------------------------------------------------------------------------
// Kernel 3: finalize. One warp per (b, side): combine 4 partials, log, W-dot.
// ---------------------------------------------------------------------------
__global__ __launch_bounds__(32) void knrm_finalize_kernel(
    const float* __restrict__ W, const float* __restrict__ bvec,
    float* __restrict__ out)
{
    const int pairI = blockIdx.x;           // 0..511
    const int k     = threadIdx.x;          // lane
    const float* base = g_part + (size_t)pairI * NSPLIT * QQ * 12;

    float part = 0.f;
    if (k < KK) {
#pragma unroll 1
        for (int q = 0; q < QQ; q++) {
            float dk = 0.f, ss = 0.f;
#pragma unroll
            for (int s = 0; s < NSPLIT; s++) {
                dk += base[s * QQ * 12 + q * 12 + k];
                ss += base[s * QQ * 12 + q * 12 + 11];
            }
            if (ss != 0.f) part += logf(dk + 1e-6f);
        }
        part *= W[k];
    }
#pragma unroll
    for (int off = 16; off; off >>= 1) part += __shfl_xor_sync(0xffffffffu, part, off);
    if (k == 0) out[pairI] = part + bvec[0];
}

// ---------------------------------------------------------------------------
// Launch. Inputs (metadata order): posdoc, negdoc, query, query_idf, emb,
// mus, sigmas, W, b. Output: [B,2] float.
// ---------------------------------------------------------------------------
extern "C" void kernel_launch(void* const* d_in, const int* in_sizes, int n_in,
                              void* d_out, int out_size) {
    const int*   posdoc = (const int*)d_in[0];
    const int*   negdoc = (const int*)d_in[1];
    const int*   query  = (const int*)d_in[2];
    // d_in[3] = query_idf (unused by the reference computation)
    const float* emb    = (const float*)d_in[4];
    const float* mus    = (const float*)d_in[5];
    const float* sigmas = (const float*)d_in[6];
    const float* W      = (const float*)d_in[7];
    const float* bvec   = (const float*)d_in[8];
    float* out = (float*)d_out;

    normalize_emb_kernel<<<(VSZ + 7) / 8, 256>>>(emb);
    knrm_main_kernel<<<BB * 2 * NSPLIT, 256>>>(posdoc, negdoc, query, mus, sigmas);
    knrm_finalize_kernel<<<BB * 2, 32>>>(W, bvec, out);
}